// round 1
// baseline (speedup 1.0000x reference)
#include <cuda_runtime.h>
#include <cstdint>

// Filtering_72773925863700
// out[b,m,n,i] = (F x)_along_m + (F x)_along_n,  F = C C^T (256x32 low-rank,
// C = ortho-normalized cos/sin basis for rfft modes [0,16), exact identity).
//
// B=8, M=N=256, I=32, fp32.

#define BATCH 8
#define MDIM 256
#define NDIM 256
#define IDIM 32
#define KM 32              // 31 real modes + 1 zero pad
#define NI (NDIM * IDIM)   // 8192

__device__ float d_C[MDIM * KM];                       // C[n][k]
__device__ float d_D1[BATCH * KM * NDIM * IDIM];       // [b][k][n][i]
__device__ float d_D2[BATCH * MDIM * KM * IDIM];       // [b][m][k][i]

// ---------------------------------------------------------------------------
// Init: C[n][j].  j=0: 1/16.  j=1..15: sqrt2/16*cos(2pi j n/256).
//                 j=16..30: sqrt2/16*sin(2pi (j-15) n/256).  j=31: 0.
// ---------------------------------------------------------------------------
__global__ void init_C_kernel() {
    int idx = blockIdx.x * 256 + threadIdx.x;   // 8192 total
    int n = idx >> 5;
    int j = idx & 31;
    const double PI = 3.14159265358979323846;
    const double AMP = 1.4142135623730951 / 16.0;   // sqrt(2)/sqrt(256)
    double v;
    if (j == 0) {
        v = 1.0 / 16.0;
    } else if (j <= 15) {
        int ph = (j * n) & 255;
        v = AMP * cos(2.0 * PI * (double)ph / 256.0);
    } else if (j <= 30) {
        int k = j - 15;
        int ph = (k * n) & 255;
        v = AMP * sin(2.0 * PI * (double)ph / 256.0);
    } else {
        v = 0.0;
    }
    d_C[idx] = (float)v;
}

// ---------------------------------------------------------------------------
// K1: D1[b,k,n,i] = sum_m C[m,k] * x[b,m,n,i]
// Per batch: [32 x 256] = C^T  times  [256 x 8192] (j = n*32+i contiguous).
// Block: (jt, b) -> tile [32k x 256j]. 256 thr: thread = (ko in 0..3)*(jq in 0..63)
// accumulates 8k x 4j.
// ---------------------------------------------------------------------------
__global__ void __launch_bounds__(256) k1_down_m(const float* __restrict__ x) {
    __shared__ float xs[16 * 256];   // [mm][j] chunk, 16 KB
    __shared__ float cs[16 * 32];    // [mm][k] chunk

    int t  = threadIdx.x;
    int b  = blockIdx.y;
    int j0 = blockIdx.x * 256;
    int jq = t & 63;   // j quad index
    int ko = t >> 6;   // k octet index

    const float* xb = x + (size_t)b * (MDIM * NI);

    float acc[8][4];
#pragma unroll
    for (int a = 0; a < 8; a++)
#pragma unroll
        for (int c = 0; c < 4; c++) acc[a][c] = 0.f;

    for (int mc = 0; mc < 16; mc++) {
        // stage x[mc*16 .. +16][j0 .. j0+256]  (4096 floats, 4 x float4/thread)
#pragma unroll
        for (int q = 0; q < 4; q++) {
            int f  = q * 256 + t;            // float4 index
            int mm = f >> 6;
            int jj = (f & 63) << 2;
            *(float4*)&xs[mm * 256 + jj] =
                *(const float4*)&xb[(size_t)(mc * 16 + mm) * NI + j0 + jj];
        }
        if (t < 128) {
            int mm = t >> 3;
            int k4 = (t & 7) << 2;
            *(float4*)&cs[mm * 32 + k4] =
                *(const float4*)&d_C[(mc * 16 + mm) * 32 + k4];
        }
        __syncthreads();

#pragma unroll
        for (int mm = 0; mm < 16; mm++) {
            float4 xv = *(float4*)&xs[mm * 256 + jq * 4];
            float4 c0 = *(float4*)&cs[mm * 32 + ko * 8];
            float4 c1 = *(float4*)&cs[mm * 32 + ko * 8 + 4];
            float cv[8] = {c0.x, c0.y, c0.z, c0.w, c1.x, c1.y, c1.z, c1.w};
#pragma unroll
            for (int a = 0; a < 8; a++) {
                acc[a][0] += cv[a] * xv.x;
                acc[a][1] += cv[a] * xv.y;
                acc[a][2] += cv[a] * xv.z;
                acc[a][3] += cv[a] * xv.w;
            }
        }
        __syncthreads();
    }

#pragma unroll
    for (int a = 0; a < 8; a++) {
        int k = ko * 8 + a;
        float4 v = make_float4(acc[a][0], acc[a][1], acc[a][2], acc[a][3]);
        *(float4*)&d_D1[((size_t)b * 32 + k) * NI + j0 + jq * 4] = v;
    }
}

// ---------------------------------------------------------------------------
// K2: D2[b,m,k,i] = sum_n C[n,k] * x[b,m,n,i]
// Block: (m-quad, b). 256 thr: (kq 0..7, iq 0..7, mloc 0..3), thread tile 4k x 4i
// dot over n, x staged in smem by 64-n chunks.
// ---------------------------------------------------------------------------
__global__ void __launch_bounds__(256) k2_down_n(const float* __restrict__ x) {
    __shared__ float zs[4 * 64 * 32];   // [mloc][nn][i]  32 KB
    __shared__ float cshr[64 * 32];     // [nn][k]         8 KB

    int t    = threadIdx.x;
    int b    = blockIdx.y;
    int m0   = blockIdx.x * 4;
    int kq   = t & 7;          // k = kq*4 + kk
    int iq   = (t >> 3) & 7;   // i = iq*4 + ii
    int mloc = t >> 6;         // 0..3

    const float* xb = x + (size_t)b * (MDIM * NI) + (size_t)m0 * NI;

    float acc[4][4];
#pragma unroll
    for (int a = 0; a < 4; a++)
#pragma unroll
        for (int c = 0; c < 4; c++) acc[a][c] = 0.f;

    for (int nc = 0; nc < 4; nc++) {
        // stage 4m x 64n x 32i = 8192 floats (8 x float4/thread), coalesced
#pragma unroll
        for (int q = 0; q < 8; q++) {
            int f  = q * 256 + t;        // float4 index
            int i4 = (f & 7) << 2;
            int nn = (f >> 3) & 63;
            int ml = f >> 9;
            *(float4*)&zs[(ml * 64 + nn) * 32 + i4] =
                *(const float4*)&xb[(size_t)ml * NI + (nc * 64 + nn) * 32 + i4];
        }
#pragma unroll
        for (int q = 0; q < 2; q++) {
            int f  = q * 256 + t;
            int k4 = (f & 7) << 2;
            int nn = f >> 3;
            *(float4*)&cshr[nn * 32 + k4] =
                *(const float4*)&d_C[(nc * 64 + nn) * 32 + k4];
        }
        __syncthreads();

#pragma unroll 8
        for (int nn = 0; nn < 64; nn++) {
            float4 z = *(float4*)&zs[(mloc * 64 + nn) * 32 + iq * 4];
            float4 c = *(float4*)&cshr[nn * 32 + kq * 4];
            float cv[4] = {c.x, c.y, c.z, c.w};
            float zv[4] = {z.x, z.y, z.z, z.w};
#pragma unroll
            for (int a = 0; a < 4; a++)
#pragma unroll
                for (int cc = 0; cc < 4; cc++)
                    acc[a][cc] += cv[a] * zv[cc];
        }
        __syncthreads();
    }

#pragma unroll
    for (int a = 0; a < 4; a++) {
        float4 v = make_float4(acc[a][0], acc[a][1], acc[a][2], acc[a][3]);
        *(float4*)&d_D2[(((size_t)b * MDIM + m0 + mloc) * 32 + kq * 4 + a) * 32 + iq * 4] = v;
    }
}

// ---------------------------------------------------------------------------
// K3: out[b,m,n,i] = sum_k C[m,k]*D1[b,k,n,i] + sum_k C[n,k]*D2[b,m,k,i]
// Block: (mt, nt, b) -> 16m x 16n x 32i output tile. 256 thr:
//   io = t&7 (i = io*4), nq = (t>>3)&3 (n = nq*4 + a), mp = t>>5 (m = mp*2 + j)
// Stream k in chunks of 8 through smem. D1/D2 are 8 MB each -> L2-resident.
// ---------------------------------------------------------------------------
__global__ void __launch_bounds__(256) k3_up(float* __restrict__ out) {
    __shared__ float d1s[8 * 16 * 32];   // [kk][nn][i]  16 KB
    __shared__ float d2s[16 * 8 * 32];   // [mm][kk][i]  16 KB
    __shared__ float cms[16 * 32];       // [mm][k]
    __shared__ float cns[16 * 33];       // [nn][k]  (pad 33 -> conflict-free scalar reads)

    int t  = threadIdx.x;
    int mt = blockIdx.x;
    int nt = blockIdx.y;
    int b  = blockIdx.z;

    int io = t & 7;
    int nq = (t >> 3) & 3;
    int mp = t >> 5;

    // stage C tiles once
    if (t < 128) {
        int mm = t >> 3;
        int k4 = (t & 7) << 2;
        *(float4*)&cms[mm * 32 + k4] =
            *(const float4*)&d_C[(mt * 16 + mm) * 32 + k4];
    } else {
        int t2 = t - 128;
        int nn = t2 >> 3;
        int k4 = (t2 & 7) << 2;
        float4 v = *(const float4*)&d_C[(nt * 16 + nn) * 32 + k4];
        cns[nn * 33 + k4 + 0] = v.x;
        cns[nn * 33 + k4 + 1] = v.y;
        cns[nn * 33 + k4 + 2] = v.z;
        cns[nn * 33 + k4 + 3] = v.w;
    }

    float acc[2][4][4];
#pragma unroll
    for (int j = 0; j < 2; j++)
#pragma unroll
        for (int a = 0; a < 4; a++)
#pragma unroll
            for (int c = 0; c < 4; c++) acc[j][a][c] = 0.f;

    for (int kc = 0; kc < 4; kc++) {
        __syncthreads();   // protects smem reuse across chunks (and C staging, iter 0)

        // stage D1 chunk: [8kk][16nn][32i] = 4096 floats
#pragma unroll
        for (int q = 0; q < 4; q++) {
            int f  = q * 256 + t;
            int i4 = (f & 7) << 2;
            int nn = (f >> 3) & 15;
            int kk = f >> 7;
            *(float4*)&d1s[(kk * 16 + nn) * 32 + i4] =
                *(const float4*)&d_D1[((size_t)b * 32 + kc * 8 + kk) * NI +
                                      (nt * 16 + nn) * 32 + i4];
        }
        // stage D2 chunk: [16mm][8kk][32i] = 4096 floats
#pragma unroll
        for (int q = 0; q < 4; q++) {
            int f  = q * 256 + t;
            int i4 = (f & 7) << 2;
            int kk = (f >> 3) & 7;
            int mm = f >> 6;
            *(float4*)&d2s[(mm * 8 + kk) * 32 + i4] =
                *(const float4*)&d_D2[(((size_t)b * MDIM + mt * 16 + mm) * 32 +
                                       kc * 8 + kk) * 32 + i4];
        }
        __syncthreads();

        // preload C_m for this thread's two m rows, 8 k's
        float cm[2][8];
#pragma unroll
        for (int j = 0; j < 2; j++) {
            float4 u0 = *(float4*)&cms[(mp * 2 + j) * 32 + kc * 8];
            float4 u1 = *(float4*)&cms[(mp * 2 + j) * 32 + kc * 8 + 4];
            cm[j][0] = u0.x; cm[j][1] = u0.y; cm[j][2] = u0.z; cm[j][3] = u0.w;
            cm[j][4] = u1.x; cm[j][5] = u1.y; cm[j][6] = u1.z; cm[j][7] = u1.w;
        }

#pragma unroll
        for (int kk = 0; kk < 8; kk++) {
            int k = kc * 8 + kk;
            float cn[4];
#pragma unroll
            for (int a = 0; a < 4; a++) cn[a] = cns[(nq * 4 + a) * 33 + k];

            float4 d1v[4];
#pragma unroll
            for (int a = 0; a < 4; a++)
                d1v[a] = *(float4*)&d1s[(kk * 16 + nq * 4 + a) * 32 + io * 4];

            float4 d2v[2];
#pragma unroll
            for (int j = 0; j < 2; j++)
                d2v[j] = *(float4*)&d2s[((mp * 2 + j) * 8 + kk) * 32 + io * 4];

#pragma unroll
            for (int j = 0; j < 2; j++) {
#pragma unroll
                for (int a = 0; a < 4; a++) {
                    acc[j][a][0] += cm[j][kk] * d1v[a].x + cn[a] * d2v[j].x;
                    acc[j][a][1] += cm[j][kk] * d1v[a].y + cn[a] * d2v[j].y;
                    acc[j][a][2] += cm[j][kk] * d1v[a].z + cn[a] * d2v[j].z;
                    acc[j][a][3] += cm[j][kk] * d1v[a].w + cn[a] * d2v[j].w;
                }
            }
        }
    }

    // write out[b][m][n][i]
#pragma unroll
    for (int j = 0; j < 2; j++) {
        int m = mt * 16 + mp * 2 + j;
#pragma unroll
        for (int a = 0; a < 4; a++) {
            int n = nt * 16 + nq * 4 + a;
            float4 v = make_float4(acc[j][a][0], acc[j][a][1],
                                   acc[j][a][2], acc[j][a][3]);
            *(float4*)&out[((size_t)b * MDIM + m) * NI + n * 32 + io * 4] = v;
        }
    }
}

// ---------------------------------------------------------------------------
extern "C" void kernel_launch(void* const* d_in, const int* in_sizes, int n_in,
                              void* d_out, int out_size) {
    const float* x = (const float*)d_in[0];
    float* out = (float*)d_out;

    init_C_kernel<<<32, 256>>>();
    k1_down_m<<<dim3(32, 8), 256>>>(x);
    k2_down_n<<<dim3(64, 8), 256>>>(x);
    k3_up<<<dim3(16, 16, 8), 256>>>(out);
}

// round 2
// speedup vs baseline: 1.1907x; 1.1907x over previous
#include <cuda_runtime.h>
#include <cstdint>

// Filtering_72773925863700
// out[b,m,n,i] = (F x)_along_m + (F x)_along_n,  F = C C^T (256x32 low-rank,
// C = ortho-normalized cos/sin basis for rfft modes [0,16), exact identity).
// B=8, M=N=256, I=32, fp32.
//
// Round 2: fma.rn.f32x2 packed FMAs everywhere (halves FMA-pipe issue count);
// k3 retiled to 4m x 4n x 4i per thread so smem wavefronts stop binding.

#define BATCH 8
#define MDIM 256
#define NDIM 256
#define IDIM 32
#define KM 32
#define NI (NDIM * IDIM)   // 8192

__device__ float d_C[MDIM * KM];                   // C[n][k]
__device__ float d_D1[BATCH * KM * NDIM * IDIM];   // [b][k][n][i]
__device__ float d_D2[BATCH * MDIM * KM * IDIM];   // [b][m][k][i]

union F4U {
    float4   f4;
    uint64_t u[2];
    float    f[4];
};

__device__ __forceinline__ uint64_t pack2(float c) {
    uint64_t r;
    asm("mov.b64 %0, {%1, %1};" : "=l"(r) : "f"(c));
    return r;
}
__device__ __forceinline__ void fma2(uint64_t& acc, uint64_t a, uint64_t b) {
    asm("fma.rn.f32x2 %0, %1, %2, %0;" : "+l"(acc) : "l"(a), "l"(b));
}

// ---------------------------------------------------------------------------
// Init C[n][j]. j=0: 1/16. j=1..15: sqrt2/16*cos(2pi j n/256).
//              j=16..30: sqrt2/16*sin(2pi (j-15) n/256). j=31: 0.
// ---------------------------------------------------------------------------
__global__ void init_C_kernel() {
    int idx = blockIdx.x * 256 + threadIdx.x;   // 8192 total
    int n = idx >> 5;
    int j = idx & 31;
    const double PI = 3.14159265358979323846;
    const double AMP = 1.4142135623730951 / 16.0;
    double v;
    if (j == 0) {
        v = 1.0 / 16.0;
    } else if (j <= 15) {
        int ph = (j * n) & 255;
        v = AMP * cos(2.0 * PI * (double)ph / 256.0);
    } else if (j <= 30) {
        int k = j - 15;
        int ph = (k * n) & 255;
        v = AMP * sin(2.0 * PI * (double)ph / 256.0);
    } else {
        v = 0.0;
    }
    d_C[idx] = (float)v;
}

// ---------------------------------------------------------------------------
// K1: D1[b,k,n,i] = sum_m C[m,k] * x[b,m,n,i]
// Block (jt, b): tile [32k x 256j]. Thread: ko=t>>6 (8 k's), jq=t&63 (4 j's).
// ---------------------------------------------------------------------------
__global__ void __launch_bounds__(256) k1_down_m(const float* __restrict__ x) {
    __shared__ float xs[16 * 256];
    __shared__ float cs[16 * 32];

    int t  = threadIdx.x;
    int b  = blockIdx.y;
    int j0 = blockIdx.x * 256;
    int jq = t & 63;
    int ko = t >> 6;

    const float* xb = x + (size_t)b * (MDIM * NI);

    uint64_t acc[8][2];
#pragma unroll
    for (int a = 0; a < 8; a++) { acc[a][0] = 0ull; acc[a][1] = 0ull; }

    for (int mc = 0; mc < 16; mc++) {
#pragma unroll
        for (int q = 0; q < 4; q++) {
            int f  = q * 256 + t;
            int mm = f >> 6;
            int jj = (f & 63) << 2;
            *(float4*)&xs[mm * 256 + jj] =
                *(const float4*)&xb[(size_t)(mc * 16 + mm) * NI + j0 + jj];
        }
        if (t < 128) {
            int mm = t >> 3;
            int k4 = (t & 7) << 2;
            *(float4*)&cs[mm * 32 + k4] =
                *(const float4*)&d_C[(mc * 16 + mm) * 32 + k4];
        }
        __syncthreads();

#pragma unroll
        for (int mm = 0; mm < 16; mm++) {
            F4U xv; xv.f4 = *(float4*)&xs[mm * 256 + jq * 4];
            F4U c0; c0.f4 = *(float4*)&cs[mm * 32 + ko * 8];
            F4U c1; c1.f4 = *(float4*)&cs[mm * 32 + ko * 8 + 4];
            float cv[8] = {c0.f[0], c0.f[1], c0.f[2], c0.f[3],
                           c1.f[0], c1.f[1], c1.f[2], c1.f[3]};
#pragma unroll
            for (int a = 0; a < 8; a++) {
                uint64_t cp = pack2(cv[a]);
                fma2(acc[a][0], cp, xv.u[0]);
                fma2(acc[a][1], cp, xv.u[1]);
            }
        }
        __syncthreads();
    }

#pragma unroll
    for (int a = 0; a < 8; a++) {
        int k = ko * 8 + a;
        F4U v; v.u[0] = acc[a][0]; v.u[1] = acc[a][1];
        *(float4*)&d_D1[((size_t)b * 32 + k) * NI + j0 + jq * 4] = v.f4;
    }
}

// ---------------------------------------------------------------------------
// K2: D2[b,m,k,i] = sum_n C[n,k] * x[b,m,n,i]
// Block (m-quad, b). Thread: kq=t&7 (4 k's), iq=(t>>3)&7 (4 i's), mloc=t>>6.
// ---------------------------------------------------------------------------
__global__ void __launch_bounds__(256) k2_down_n(const float* __restrict__ x) {
    __shared__ float zs[4 * 64 * 32];
    __shared__ float cshr[64 * 32];

    int t    = threadIdx.x;
    int b    = blockIdx.y;
    int m0   = blockIdx.x * 4;
    int kq   = t & 7;
    int iq   = (t >> 3) & 7;
    int mloc = t >> 6;

    const float* xb = x + (size_t)b * (MDIM * NI) + (size_t)m0 * NI;

    uint64_t acc[4][2];
#pragma unroll
    for (int a = 0; a < 4; a++) { acc[a][0] = 0ull; acc[a][1] = 0ull; }

    for (int nc = 0; nc < 4; nc++) {
#pragma unroll
        for (int q = 0; q < 8; q++) {
            int f  = q * 256 + t;
            int i4 = (f & 7) << 2;
            int nn = (f >> 3) & 63;
            int ml = f >> 9;
            *(float4*)&zs[(ml * 64 + nn) * 32 + i4] =
                *(const float4*)&xb[(size_t)ml * NI + (nc * 64 + nn) * 32 + i4];
        }
#pragma unroll
        for (int q = 0; q < 2; q++) {
            int f  = q * 256 + t;
            int k4 = (f & 7) << 2;
            int nn = f >> 3;
            *(float4*)&cshr[nn * 32 + k4] =
                *(const float4*)&d_C[(nc * 64 + nn) * 32 + k4];
        }
        __syncthreads();

#pragma unroll 8
        for (int nn = 0; nn < 64; nn++) {
            F4U z; z.f4 = *(float4*)&zs[(mloc * 64 + nn) * 32 + iq * 4];
            F4U c; c.f4 = *(float4*)&cshr[nn * 32 + kq * 4];
#pragma unroll
            for (int a = 0; a < 4; a++) {
                uint64_t cp = pack2(c.f[a]);
                fma2(acc[a][0], cp, z.u[0]);
                fma2(acc[a][1], cp, z.u[1]);
            }
        }
        __syncthreads();
    }

#pragma unroll
    for (int a = 0; a < 4; a++) {
        F4U v; v.u[0] = acc[a][0]; v.u[1] = acc[a][1];
        *(float4*)&d_D2[(((size_t)b * MDIM + m0 + mloc) * 32 + kq * 4 + a) * 32 + iq * 4] = v.f4;
    }
}

// ---------------------------------------------------------------------------
// K3: out[b,m,n,i] = sum_k C[m,k]*D1[b,k,n,i] + sum_k C[n,k]*D2[b,m,k,i]
// Block (mt, nt, b): 32m x 16n x 32i tile. Thread: io=t&7 (4 i),
// nq=(t>>3)&3 (4 n), mp=t>>5 (4 m). k streamed in chunks of 4.
// ---------------------------------------------------------------------------
__global__ void __launch_bounds__(256, 2) k3_up(float* __restrict__ out) {
    __shared__ float d1s[4 * 16 * 32];   // [kk][nn][i]   8 KB
    __shared__ float d2s[32 * 4 * 32];   // [mm][kk][i]  16 KB
    __shared__ float cms[32 * 32];       // [mm][k]       4 KB
    __shared__ float cns[16 * 33];       // [nn][k] padded

    int t  = threadIdx.x;
    int mt = blockIdx.x;
    int nt = blockIdx.y;
    int b  = blockIdx.z;

    int io = t & 7;
    int nq = (t >> 3) & 3;
    int mp = t >> 5;

    // Stage C tiles once.
    {
        int mm = t >> 3;
        int k4 = (t & 7) << 2;
        *(float4*)&cms[mm * 32 + k4] =
            *(const float4*)&d_C[(mt * 32 + mm) * 32 + k4];
    }
    if (t < 128) {
        int nn = t >> 3;
        int k4 = (t & 7) << 2;
        float4 v = *(const float4*)&d_C[(nt * 16 + nn) * 32 + k4];
        cns[nn * 33 + k4 + 0] = v.x;
        cns[nn * 33 + k4 + 1] = v.y;
        cns[nn * 33 + k4 + 2] = v.z;
        cns[nn * 33 + k4 + 3] = v.w;
    }

    uint64_t acc[4][4][2];
#pragma unroll
    for (int j = 0; j < 4; j++)
#pragma unroll
        for (int a = 0; a < 4; a++) { acc[j][a][0] = 0ull; acc[j][a][1] = 0ull; }

    for (int kc = 0; kc < 8; kc++) {
        __syncthreads();   // protect smem reuse (and C staging on iter 0)

        // stage D1 chunk: [4kk][16nn][32i] = 2048 floats
#pragma unroll
        for (int q = 0; q < 2; q++) {
            int f  = q * 256 + t;
            int i4 = (f & 7) << 2;
            int nn = (f >> 3) & 15;
            int kk = f >> 7;
            *(float4*)&d1s[(kk * 16 + nn) * 32 + i4] =
                *(const float4*)&d_D1[((size_t)b * 32 + kc * 4 + kk) * NI +
                                      (nt * 16 + nn) * 32 + i4];
        }
        // stage D2 chunk: [32mm][4kk][32i] = 4096 floats
#pragma unroll
        for (int q = 0; q < 4; q++) {
            int f  = q * 256 + t;
            int i4 = (f & 7) << 2;
            int kk = (f >> 3) & 3;
            int mm = f >> 5;
            *(float4*)&d2s[(mm * 4 + kk) * 32 + i4] =
                *(const float4*)&d_D2[(((size_t)b * MDIM + mt * 32 + mm) * 32 +
                                       kc * 4 + kk) * 32 + i4];
        }
        __syncthreads();

#pragma unroll
        for (int kk = 0; kk < 4; kk++) {
            int k = kc * 4 + kk;

            uint64_t cmp[4], cnp[4];
#pragma unroll
            for (int j = 0; j < 4; j++)
                cmp[j] = pack2(cms[(mp * 4 + j) * 32 + k]);
#pragma unroll
            for (int a = 0; a < 4; a++)
                cnp[a] = pack2(cns[(nq * 4 + a) * 33 + k]);

            F4U d1v[4], d2v[4];
#pragma unroll
            for (int a = 0; a < 4; a++)
                d1v[a].f4 = *(float4*)&d1s[(kk * 16 + nq * 4 + a) * 32 + io * 4];
#pragma unroll
            for (int j = 0; j < 4; j++)
                d2v[j].f4 = *(float4*)&d2s[((mp * 4 + j) * 4 + kk) * 32 + io * 4];

#pragma unroll
            for (int j = 0; j < 4; j++) {
#pragma unroll
                for (int a = 0; a < 4; a++) {
                    fma2(acc[j][a][0], cmp[j], d1v[a].u[0]);
                    fma2(acc[j][a][0], cnp[a], d2v[j].u[0]);
                    fma2(acc[j][a][1], cmp[j], d1v[a].u[1]);
                    fma2(acc[j][a][1], cnp[a], d2v[j].u[1]);
                }
            }
        }
    }

#pragma unroll
    for (int j = 0; j < 4; j++) {
        int m = mt * 32 + mp * 4 + j;
#pragma unroll
        for (int a = 0; a < 4; a++) {
            int n = nt * 16 + nq * 4 + a;
            F4U v; v.u[0] = acc[j][a][0]; v.u[1] = acc[j][a][1];
            *(float4*)&out[((size_t)b * MDIM + m) * NI + n * 32 + io * 4] = v.f4;
        }
    }
}

// ---------------------------------------------------------------------------
extern "C" void kernel_launch(void* const* d_in, const int* in_sizes, int n_in,
                              void* d_out, int out_size) {
    const float* x = (const float*)d_in[0];
    float* out = (float*)d_out;

    init_C_kernel<<<32, 256>>>();
    k1_down_m<<<dim3(32, 8), 256>>>(x);
    k2_down_n<<<dim3(64, 8), 256>>>(x);
    k3_up<<<dim3(8, 16, 8), 256>>>(out);
}

// round 6
// speedup vs baseline: 1.3350x; 1.1212x over previous
#include <cuda_runtime.h>
#include <cstdint>

// Filtering_72773925863700
// out[b,m,n,i] = (F x)_along_m + (F x)_along_n,  F = C C^T (256x32 low-rank,
// C = ortho-normalized cos/sin basis for rfft modes [0,16), exact identity).
// B=8, M=N=256, I=32, fp32.
//
// Round 6: Round-5 register-prefetch pipeline with the k3 d2-prefetch OOB
// fixed (q<8 -> q<4; mm was reaching 31 against a 16-row tile, corrupting
// smem + reading past d_D2). Plain LDG/STS only.

#define BATCH 8
#define MDIM 256
#define NDIM 256
#define IDIM 32
#define KM 32
#define NI (NDIM * IDIM)   // 8192

__device__ float d_C[MDIM * KM];                   // C[n][k]
__device__ float d_D1[BATCH * KM * NDIM * IDIM];   // [b][k][n][i]
__device__ float d_D2[BATCH * MDIM * KM * IDIM];   // [b][m][k][i]

union F4U { float4 f4; uint64_t u[2]; float f[4]; };
union F2U { float2 f2; uint64_t u; };

__device__ __forceinline__ uint64_t pack2(float c) {
    uint64_t r;
    asm("mov.b64 %0, {%1, %1};" : "=l"(r) : "f"(c));
    return r;
}
__device__ __forceinline__ void fma2(uint64_t& acc, uint64_t a, uint64_t b) {
    asm("fma.rn.f32x2 %0, %1, %2, %0;" : "+l"(acc) : "l"(a), "l"(b));
}

// ---------------------------------------------------------------------------
// Init C[n][j]. j=0: 1/16. j=1..15: sqrt2/16*cos(2pi j n/256).
//              j=16..30: sqrt2/16*sin(2pi (j-15) n/256). j=31: 0.
// ---------------------------------------------------------------------------
__global__ void init_C_kernel() {
    int idx = blockIdx.x * 256 + threadIdx.x;   // 8192 total
    int n = idx >> 5;
    int j = idx & 31;
    const double PI = 3.14159265358979323846;
    const double AMP = 1.4142135623730951 / 16.0;
    double v;
    if (j == 0) {
        v = 1.0 / 16.0;
    } else if (j <= 15) {
        int ph = (j * n) & 255;
        v = AMP * cos(2.0 * PI * (double)ph / 256.0);
    } else if (j <= 30) {
        int k = j - 15;
        int ph = (k * n) & 255;
        v = AMP * sin(2.0 * PI * (double)ph / 256.0);
    } else {
        v = 0.0;
    }
    d_C[idx] = (float)v;
}

// ---------------------------------------------------------------------------
// K1: D1[b,k,n,i] = sum_m C[m,k] * x[b,m,n,i]
// Block (jt, b): tile [32k x 256j]. Thread: ko=t>>6 (8 k's), jq=t&63 (4 j's).
// Register-prefetch pipelined over 16 m-chunks.
// ---------------------------------------------------------------------------
__global__ void __launch_bounds__(256) k1_down_m(const float* __restrict__ x) {
    __shared__ __align__(16) float xs[16 * 256];   // 16 KB
    __shared__ __align__(16) float cs[16 * 32];    //  2 KB

    int t  = threadIdx.x;
    int b  = blockIdx.y;
    int j0 = blockIdx.x * 256;
    int jq = t & 63;
    int ko = t >> 6;

    const float* xb = x + (size_t)b * (MDIM * NI);

    float4 px[4];
    float4 pc;

    auto ld = [&](int mc) {
#pragma unroll
        for (int q = 0; q < 4; q++) {
            int f  = q * 256 + t;
            int mm = f >> 6;
            int jj = (f & 63) << 2;
            px[q] = *(const float4*)&xb[(size_t)(mc * 16 + mm) * NI + j0 + jj];
        }
        if (t < 128)
            pc = *(const float4*)&d_C[(mc * 16 + (t >> 3)) * 32 + ((t & 7) << 2)];
    };
    auto st = [&]() {
#pragma unroll
        for (int q = 0; q < 4; q++) {
            int f  = q * 256 + t;
            int mm = f >> 6;
            int jj = (f & 63) << 2;
            *(float4*)&xs[mm * 256 + jj] = px[q];
        }
        if (t < 128)
            *(float4*)&cs[(t >> 3) * 32 + ((t & 7) << 2)] = pc;
    };

    uint64_t acc[8][2];
#pragma unroll
    for (int a = 0; a < 8; a++) { acc[a][0] = 0ull; acc[a][1] = 0ull; }

    ld(0);
    for (int mc = 0; mc < 16; mc++) {
        if (mc > 0) __syncthreads();        // readers of smem done
        st();
        if (mc < 15) ld(mc + 1);            // LDG in flight during compute
        __syncthreads();

#pragma unroll
        for (int mm = 0; mm < 16; mm++) {
            F4U xv; xv.f4 = *(const float4*)&xs[mm * 256 + jq * 4];
            F4U c0; c0.f4 = *(const float4*)&cs[mm * 32 + ko * 8];
            F4U c1; c1.f4 = *(const float4*)&cs[mm * 32 + ko * 8 + 4];
            float cv[8] = {c0.f[0], c0.f[1], c0.f[2], c0.f[3],
                           c1.f[0], c1.f[1], c1.f[2], c1.f[3]};
#pragma unroll
            for (int a = 0; a < 8; a++) {
                uint64_t cp = pack2(cv[a]);
                fma2(acc[a][0], cp, xv.u[0]);
                fma2(acc[a][1], cp, xv.u[1]);
            }
        }
    }

#pragma unroll
    for (int a = 0; a < 8; a++) {
        int k = ko * 8 + a;
        F4U v; v.u[0] = acc[a][0]; v.u[1] = acc[a][1];
        *(float4*)&d_D1[((size_t)b * 32 + k) * NI + j0 + jq * 4] = v.f4;
    }
}

// ---------------------------------------------------------------------------
// K2: D2[b,m,k,i] = sum_n C[n,k] * x[b,m,n,i]
// Block (m-quad, b). Thread: kq=t&7 (4 k's), iq=(t>>3)&7 (4 i's), mloc=t>>6.
// Register-prefetch pipelined over 8 n-chunks of 32.
// ---------------------------------------------------------------------------
__global__ void __launch_bounds__(256) k2_down_n(const float* __restrict__ x) {
    __shared__ __align__(16) float zs[4 * 32 * 32];   // 16 KB
    __shared__ __align__(16) float cs2[32 * 32];      //  4 KB

    int t    = threadIdx.x;
    int b    = blockIdx.y;
    int m0   = blockIdx.x * 4;
    int kq   = t & 7;
    int iq   = (t >> 3) & 7;
    int mloc = t >> 6;

    const float* xb = x + (size_t)b * (MDIM * NI) + (size_t)m0 * NI;

    float4 pz[4];
    float4 pc;

    auto ld = [&](int nc) {
#pragma unroll
        for (int q = 0; q < 4; q++) {
            int f  = q * 256 + t;
            int i4 = (f & 7) << 2;
            int nn = (f >> 3) & 31;
            int ml = f >> 8;
            pz[q] = *(const float4*)&xb[(size_t)ml * NI + (nc * 32 + nn) * 32 + i4];
        }
        pc = *(const float4*)&d_C[(nc * 32 + (t >> 3)) * 32 + ((t & 7) << 2)];
    };
    auto st = [&]() {
#pragma unroll
        for (int q = 0; q < 4; q++) {
            int f  = q * 256 + t;
            int i4 = (f & 7) << 2;
            int nn = (f >> 3) & 31;
            int ml = f >> 8;
            *(float4*)&zs[(ml * 32 + nn) * 32 + i4] = pz[q];
        }
        *(float4*)&cs2[(t >> 3) * 32 + ((t & 7) << 2)] = pc;
    };

    uint64_t acc[4][2];
#pragma unroll
    for (int a = 0; a < 4; a++) { acc[a][0] = 0ull; acc[a][1] = 0ull; }

    ld(0);
    for (int nc = 0; nc < 8; nc++) {
        if (nc > 0) __syncthreads();
        st();
        if (nc < 7) ld(nc + 1);
        __syncthreads();

#pragma unroll 8
        for (int nn = 0; nn < 32; nn++) {
            F4U z; z.f4 = *(const float4*)&zs[(mloc * 32 + nn) * 32 + iq * 4];
            F4U c; c.f4 = *(const float4*)&cs2[nn * 32 + kq * 4];
#pragma unroll
            for (int a = 0; a < 4; a++) {
                uint64_t cp = pack2(c.f[a]);
                fma2(acc[a][0], cp, z.u[0]);
                fma2(acc[a][1], cp, z.u[1]);
            }
        }
    }

#pragma unroll
    for (int a = 0; a < 4; a++) {
        F4U v; v.u[0] = acc[a][0]; v.u[1] = acc[a][1];
        *(float4*)&d_D2[(((size_t)b * MDIM + m0 + mloc) * 32 + kq * 4 + a) * 32 + iq * 4] = v.f4;
    }
}

// ---------------------------------------------------------------------------
// K3: out[b,m,n,i] = sum_k C[m,k]*D1[b,k,n,i] + sum_k C[n,k]*D2[b,m,k,i]
// Block (mt, nt, b): 16m x 16n x 32i tile, 128 threads.
// Thread: io=t&15 (2 i), nq=(t>>4)&3 (4 n), mp=t>>6 (8 m).
// k streamed in chunks of 4, register-prefetch pipelined. Coeffs staged
// transposed ([k][mm], [k][nn]) so per-kk coeff loads are float4/warp-uniform.
// ---------------------------------------------------------------------------
__global__ void __launch_bounds__(128) k3_up(float* __restrict__ out) {
    __shared__ __align__(16) float d1s[4 * 16 * 32];   // [kk][nn][i]  8 KB
    __shared__ __align__(16) float d2s[16 * 4 * 32];   // [mm][kk][i]  8 KB
    __shared__ __align__(16) float cms2[32 * 16];      // [k][mm]      2 KB
    __shared__ __align__(16) float cns2[32 * 16];      // [k][nn]      2 KB

    int t  = threadIdx.x;
    int mt = blockIdx.x;
    int nt = blockIdx.y;
    int b  = blockIdx.z;

    int io = t & 15;
    int nq = (t >> 4) & 3;
    int mp = t >> 6;

    // Stage transposed C tiles once (512 each, 4 scalar loads/thread).
#pragma unroll
    for (int q = 0; q < 4; q++) {
        int idx = q * 128 + t;
        int k  = idx >> 4;
        int mm = idx & 15;
        cms2[idx] = d_C[(mt * 16 + mm) * 32 + k];
        cns2[idx] = d_C[(nt * 16 + mm) * 32 + k];
    }

    float4 p1[4], p2[4];

    auto ld = [&](int kc) {
        // d1 chunk: 4kk x 16nn x 32i = 2048 floats = 512 float4; 128thr x 4
#pragma unroll
        for (int q = 0; q < 4; q++) {
            int f  = q * 128 + t;
            int i4 = (f & 7) << 2;
            int nn = (f >> 3) & 15;
            int kk = f >> 7;
            p1[q] = *(const float4*)&d_D1[((size_t)b * 32 + kc * 4 + kk) * NI +
                                          (nt * 16 + nn) * 32 + i4];
        }
        // d2 chunk: 16mm x 4kk x 32i = 2048 floats = 512 float4; 128thr x 4
#pragma unroll
        for (int q = 0; q < 4; q++) {
            int f  = q * 128 + t;
            int i4 = (f & 7) << 2;
            int kk = (f >> 3) & 3;
            int mm = f >> 5;     // 0..15
            p2[q] = *(const float4*)&d_D2[(((size_t)b * MDIM + mt * 16 + mm) * 32 +
                                           kc * 4 + kk) * 32 + i4];
        }
    };
    auto st = [&]() {
#pragma unroll
        for (int q = 0; q < 4; q++) {
            int f  = q * 128 + t;
            int i4 = (f & 7) << 2;
            int nn = (f >> 3) & 15;
            int kk = f >> 7;
            *(float4*)&d1s[(kk * 16 + nn) * 32 + i4] = p1[q];
        }
#pragma unroll
        for (int q = 0; q < 4; q++) {
            int f  = q * 128 + t;
            int i4 = (f & 7) << 2;
            int kk = (f >> 3) & 3;
            int mm = f >> 5;
            *(float4*)&d2s[(mm * 4 + kk) * 32 + i4] = p2[q];
        }
    };

    uint64_t acc[8][4];
#pragma unroll
    for (int j = 0; j < 8; j++)
#pragma unroll
        for (int a = 0; a < 4; a++) acc[j][a] = 0ull;

    ld(0);
    for (int kc = 0; kc < 8; kc++) {
        if (kc > 0) __syncthreads();    // readers done with smem
        st();
        if (kc < 7) ld(kc + 1);         // next chunk's LDGs overlap compute
        __syncthreads();                // also orders cms2/cns2 staging (iter 0)

#pragma unroll
        for (int kk = 0; kk < 4; kk++) {
            int k = kc * 4 + kk;

            F4U cmA, cmB, cnv;
            cmA.f4 = *(const float4*)&cms2[k * 16 + mp * 8];
            cmB.f4 = *(const float4*)&cms2[k * 16 + mp * 8 + 4];
            cnv.f4 = *(const float4*)&cns2[k * 16 + nq * 4];

            uint64_t cnp[4];
#pragma unroll
            for (int a = 0; a < 4; a++) cnp[a] = pack2(cnv.f[a]);

            F2U d1v[4], d2v[8];
#pragma unroll
            for (int a = 0; a < 4; a++)
                d1v[a].f2 = *(const float2*)&d1s[(kk * 16 + nq * 4 + a) * 32 + io * 2];
#pragma unroll
            for (int j = 0; j < 8; j++)
                d2v[j].f2 = *(const float2*)&d2s[((mp * 8 + j) * 4 + kk) * 32 + io * 2];

            float cmf[8] = {cmA.f[0], cmA.f[1], cmA.f[2], cmA.f[3],
                            cmB.f[0], cmB.f[1], cmB.f[2], cmB.f[3]};
#pragma unroll
            for (int j = 0; j < 8; j++) {
                uint64_t cmp = pack2(cmf[j]);
#pragma unroll
                for (int a = 0; a < 4; a++) {
                    fma2(acc[j][a], cmp, d1v[a].u);
                    fma2(acc[j][a], cnp[a], d2v[j].u);
                }
            }
        }
    }

#pragma unroll
    for (int j = 0; j < 8; j++) {
        int m = mt * 16 + mp * 8 + j;
#pragma unroll
        for (int a = 0; a < 4; a++) {
            int n = nt * 16 + nq * 4 + a;
            F2U v; v.u = acc[j][a];
            *(float2*)&out[((size_t)b * MDIM + m) * NI + n * 32 + io * 2] = v.f2;
        }
    }
}

// ---------------------------------------------------------------------------
extern "C" void kernel_launch(void* const* d_in, const int* in_sizes, int n_in,
                              void* d_out, int out_size) {
    const float* x = (const float*)d_in[0];
    float* out = (float*)d_out;

    init_C_kernel<<<32, 256>>>();
    k1_down_m<<<dim3(32, 8), 256>>>(x);
    k2_down_n<<<dim3(64, 8), 256>>>(x);
    k3_up<<<dim3(16, 16, 8), 128>>>(out);
}

// round 7
// speedup vs baseline: 1.5191x; 1.1379x over previous
#include <cuda_runtime.h>
#include <cstdint>

// Filtering_72773925863700
// out[b,m,n,i] = (F x)_along_m + (F x)_along_n,  F = C C^T (256x32 low-rank,
// C = ortho-normalized cos/sin basis for rfft modes [0,16), exact identity).
// B=8, M=N=256, I=32, fp32.
//
// Round 7: cp.async.bulk (UBLKCP) + mbarrier double-buffered staging in all
// kernels — DMA writes smem directly, removing LDG+STS wavefronts from the
// L1tex port and freeing ~50 prefetch registers. k1/k2 retiled so data LDS
// is broadcast-dedup'd; k3 keeps the audited R6 inner loop.

#define BATCH 8
#define MDIM 256
#define NDIM 256
#define IDIM 32
#define KM 32
#define NI (NDIM * IDIM)   // 8192

__device__ float d_C[MDIM * KM];                   // C[n][k]
__device__ float d_D1[BATCH * KM * NDIM * IDIM];   // [b][k][n][i]
__device__ float d_D2[BATCH * MDIM * KM * IDIM];   // [b][m][k][i]

union F4U { float4 f4; uint64_t u[2]; float f[4]; };
union F2U { float2 f2; uint64_t u; };

__device__ __forceinline__ uint64_t pack2(float c) {
    uint64_t r;
    asm("mov.b64 %0, {%1, %1};" : "=l"(r) : "f"(c));
    return r;
}
__device__ __forceinline__ void fma2(uint64_t& acc, uint64_t a, uint64_t b) {
    asm("fma.rn.f32x2 %0, %1, %2, %0;" : "+l"(acc) : "l"(a), "l"(b));
}
__device__ __forceinline__ uint32_t sm_addr(const void* p) {
    uint32_t a;
    asm("{ .reg .u64 t; cvta.to.shared.u64 t, %1; cvt.u32.u64 %0, t; }"
        : "=r"(a) : "l"(p));
    return a;
}
__device__ __forceinline__ void mbar_init(uint32_t mbar, uint32_t count) {
    asm volatile("mbarrier.init.shared.b64 [%0], %1;" :: "r"(mbar), "r"(count) : "memory");
}
__device__ __forceinline__ void mbar_expect(uint32_t mbar, uint32_t bytes) {
    asm volatile("mbarrier.arrive.expect_tx.shared.b64 _, [%0], %1;"
                 :: "r"(mbar), "r"(bytes) : "memory");
}
__device__ __forceinline__ void bulk_g2s(uint32_t dst, const void* src,
                                         uint32_t bytes, uint32_t mbar) {
    asm volatile(
        "cp.async.bulk.shared::cta.global.mbarrier::complete_tx::bytes [%0], [%1], %2, [%3];"
        :: "r"(dst), "l"(src), "r"(bytes), "r"(mbar) : "memory");
}
__device__ __forceinline__ void mbar_wait(uint32_t mbar, uint32_t parity) {
    asm volatile(
        "{\n\t"
        ".reg .pred P1;\n\t"
        "WAIT_LOOP_%=:\n\t"
        "mbarrier.try_wait.parity.acquire.cta.shared::cta.b64 P1, [%0], %1;\n\t"
        "@P1 bra.uni WAIT_DONE_%=;\n\t"
        "bra.uni WAIT_LOOP_%=;\n\t"
        "WAIT_DONE_%=:\n\t"
        "}"
        :: "r"(mbar), "r"(parity) : "memory");
}

// ---------------------------------------------------------------------------
// Init C[n][j]. j=0: 1/16. j=1..15: sqrt2/16*cos(2pi j n/256).
//              j=16..30: sqrt2/16*sin(2pi (j-15) n/256). j=31: 0.
// ---------------------------------------------------------------------------
__global__ void init_C_kernel() {
    int idx = blockIdx.x * 256 + threadIdx.x;   // 8192 total
    int n = idx >> 5;
    int j = idx & 31;
    const double PI = 3.14159265358979323846;
    const double AMP = 1.4142135623730951 / 16.0;
    double v;
    if (j == 0) {
        v = 1.0 / 16.0;
    } else if (j <= 15) {
        int ph = (j * n) & 255;
        v = AMP * cos(2.0 * PI * (double)ph / 256.0);
    } else if (j <= 30) {
        int k = j - 15;
        int ph = (k * n) & 255;
        v = AMP * sin(2.0 * PI * (double)ph / 256.0);
    } else {
        v = 0.0;
    }
    d_C[idx] = (float)v;
}

// ---------------------------------------------------------------------------
// K1: D1[b,k,n,i] = sum_m C[m,k] * x[b,m,n,i]
// Block (jt, b): tile [32k x 256j], 128 thr. Thread: ko=t>>5 (8 k's),
// jq=t&31 (j quads at jq*4 and 128+jq*4 — split avoids 32B-stride conflicts).
// Bulk-async double-buffered over 32 m-chunks of 8.
// ---------------------------------------------------------------------------
__global__ void __launch_bounds__(128) k1_down_m(const float* __restrict__ x) {
    __shared__ __align__(128) float xs[2][8 * 256];   // 8 KB each
    __shared__ __align__(128) float cs[2][8 * 32];    // 1 KB each
    __shared__ __align__(8) uint64_t mbar[2];

    int t  = threadIdx.x;
    int b  = blockIdx.y;
    int j0 = blockIdx.x * 256;
    int jq = t & 31;
    int ko = t >> 5;   // 0..3

    const float* xb = x + (size_t)b * (MDIM * NI);
    uint32_t mb0 = sm_addr(&mbar[0]);
    uint32_t mb1 = sm_addr(&mbar[1]);

    if (t == 0) { mbar_init(mb0, 1); mbar_init(mb1, 1); }
    __syncthreads();

    const uint32_t CHUNK_BYTES = 8 * 256 * 4 + 8 * 32 * 4;   // 9216

    auto issue = [&](int mc, int s) {
        uint32_t mb = s ? mb1 : mb0;
        mbar_expect(mb, CHUNK_BYTES);
#pragma unroll
        for (int mm = 0; mm < 8; mm++)
            bulk_g2s(sm_addr(&xs[s][mm * 256]),
                     &xb[(size_t)(mc * 8 + mm) * NI + j0], 256 * 4, mb);
        bulk_g2s(sm_addr(&cs[s][0]), &d_C[mc * 8 * 32], 8 * 32 * 4, mb);
    };

    uint64_t acc[8][4];
#pragma unroll
    for (int a = 0; a < 8; a++)
#pragma unroll
        for (int q = 0; q < 4; q++) acc[a][q] = 0ull;

    if (t == 0) issue(0, 0);
    for (int mc = 0; mc < 32; mc++) {
        int s = mc & 1;
        if (mc + 1 < 32) {
            __syncthreads();                 // readers done with buffer s^1
            if (t == 0) issue(mc + 1, s ^ 1);
        }
        mbar_wait(s ? mb1 : mb0, (mc >> 1) & 1);

        const float* xsb = xs[s];
        const float* csb = cs[s];
#pragma unroll
        for (int mm = 0; mm < 8; mm++) {
            F4U x0; x0.f4 = *(const float4*)&xsb[mm * 256 + jq * 4];
            F4U x1; x1.f4 = *(const float4*)&xsb[mm * 256 + 128 + jq * 4];
            F4U c0; c0.f4 = *(const float4*)&csb[mm * 32 + ko * 8];
            F4U c1; c1.f4 = *(const float4*)&csb[mm * 32 + ko * 8 + 4];
            float cv[8] = {c0.f[0], c0.f[1], c0.f[2], c0.f[3],
                           c1.f[0], c1.f[1], c1.f[2], c1.f[3]};
#pragma unroll
            for (int a = 0; a < 8; a++) {
                uint64_t cp = pack2(cv[a]);
                fma2(acc[a][0], cp, x0.u[0]);
                fma2(acc[a][1], cp, x0.u[1]);
                fma2(acc[a][2], cp, x1.u[0]);
                fma2(acc[a][3], cp, x1.u[1]);
            }
        }
    }

#pragma unroll
    for (int a = 0; a < 8; a++) {
        int k = ko * 8 + a;
        F4U v0; v0.u[0] = acc[a][0]; v0.u[1] = acc[a][1];
        F4U v1; v1.u[0] = acc[a][2]; v1.u[1] = acc[a][3];
        *(float4*)&d_D1[((size_t)b * 32 + k) * NI + j0 + jq * 4]       = v0.f4;
        *(float4*)&d_D1[((size_t)b * 32 + k) * NI + j0 + 128 + jq * 4] = v1.f4;
    }
}

// ---------------------------------------------------------------------------
// K2: D2[b,m,k,i] = sum_n C[n,k] * x[b,m,n,i]
// Block (mt of 8 m, b), 256 thr. Thread: kq=t&3 (8 k), iq=(t>>2)&7 (4 i),
// ml=t>>5 (warp-uniform m). Per nn per warp: z 1 wf + c 2 wf vs 16 fma2.
// Bulk-async double-buffered over 16 n-chunks of 16.
// ---------------------------------------------------------------------------
__global__ void __launch_bounds__(256) k2_down_n(const float* __restrict__ x) {
    __shared__ __align__(128) float zs[2][8 * 16 * 32];   // 16 KB each
    __shared__ __align__(128) float ch[2][16 * 32];       //  2 KB each
    __shared__ __align__(8) uint64_t mbar[2];

    int t  = threadIdx.x;
    int b  = blockIdx.y;
    int m0 = blockIdx.x * 8;
    int kq = t & 3;
    int iq = (t >> 2) & 7;
    int ml = t >> 5;   // 0..7, warp-uniform

    const float* xb = x + (size_t)b * (MDIM * NI) + (size_t)m0 * NI;
    uint32_t mb0 = sm_addr(&mbar[0]);
    uint32_t mb1 = sm_addr(&mbar[1]);

    if (t == 0) { mbar_init(mb0, 1); mbar_init(mb1, 1); }
    __syncthreads();

    const uint32_t CHUNK_BYTES = 8 * 16 * 32 * 4 + 16 * 32 * 4;   // 18432

    auto issue = [&](int nc, int s) {
        uint32_t mb = s ? mb1 : mb0;
        mbar_expect(mb, CHUNK_BYTES);
#pragma unroll
        for (int m2 = 0; m2 < 8; m2++)
            bulk_g2s(sm_addr(&zs[s][m2 * 16 * 32]),
                     &xb[(size_t)m2 * NI + nc * 16 * 32], 16 * 32 * 4, mb);
        bulk_g2s(sm_addr(&ch[s][0]), &d_C[nc * 16 * 32], 16 * 32 * 4, mb);
    };

    uint64_t acc[8][2];
#pragma unroll
    for (int kk = 0; kk < 8; kk++) { acc[kk][0] = 0ull; acc[kk][1] = 0ull; }

    if (t == 0) issue(0, 0);
    for (int nc = 0; nc < 16; nc++) {
        int s = nc & 1;
        if (nc + 1 < 16) {
            __syncthreads();
            if (t == 0) issue(nc + 1, s ^ 1);
        }
        mbar_wait(s ? mb1 : mb0, (nc >> 1) & 1);

        const float* zb = zs[s];
        const float* cb = ch[s];
#pragma unroll
        for (int nn = 0; nn < 16; nn++) {
            F4U z; z.f4 = *(const float4*)&zb[(ml * 16 + nn) * 32 + iq * 4];
            F4U c0; c0.f4 = *(const float4*)&cb[nn * 32 + kq * 8];
            F4U c1; c1.f4 = *(const float4*)&cb[nn * 32 + kq * 8 + 4];
            float cv[8] = {c0.f[0], c0.f[1], c0.f[2], c0.f[3],
                           c1.f[0], c1.f[1], c1.f[2], c1.f[3]};
#pragma unroll
            for (int kk = 0; kk < 8; kk++) {
                uint64_t cp = pack2(cv[kk]);
                fma2(acc[kk][0], cp, z.u[0]);
                fma2(acc[kk][1], cp, z.u[1]);
            }
        }
    }

#pragma unroll
    for (int kk = 0; kk < 8; kk++) {
        int k = kq * 8 + kk;
        F4U v; v.u[0] = acc[kk][0]; v.u[1] = acc[kk][1];
        *(float4*)&d_D2[(((size_t)b * MDIM + m0 + ml) * 32 + k) * 32 + iq * 4] = v.f4;
    }
}

// ---------------------------------------------------------------------------
// K3: out[b,m,n,i] = sum_k C[m,k]*D1[b,k,n,i] + sum_k C[n,k]*D2[b,m,k,i]
// Block (mt, nt, b): 16m x 16n x 32i tile, 128 threads.
// Thread: io=t&15 (2 i), nq=(t>>4)&3 (4 n), mp=t>>6 (8 m, warp-uniform).
// k streamed in chunks of 4, bulk-async double-buffered.
// ---------------------------------------------------------------------------
__global__ void __launch_bounds__(128) k3_up(float* __restrict__ out) {
    __shared__ __align__(128) float d1s[2][4 * 16 * 32];   // 8 KB each
    __shared__ __align__(128) float d2s[2][16 * 4 * 32];   // 8 KB each
    __shared__ __align__(16) float cms2[32 * 16];          // [k][mm]
    __shared__ __align__(16) float cns2[32 * 16];          // [k][nn]
    __shared__ __align__(8) uint64_t mbar[2];

    int t  = threadIdx.x;
    int mt = blockIdx.x;
    int nt = blockIdx.y;
    int b  = blockIdx.z;

    int io = t & 15;
    int nq = (t >> 4) & 3;
    int mp = t >> 6;

    uint32_t mb0 = sm_addr(&mbar[0]);
    uint32_t mb1 = sm_addr(&mbar[1]);
    if (t == 0) { mbar_init(mb0, 1); mbar_init(mb1, 1); }

    // Stage transposed C tiles (512 each, 4 scalar loads/thread).
#pragma unroll
    for (int q = 0; q < 4; q++) {
        int idx = q * 128 + t;
        int k  = idx >> 4;
        int mm = idx & 15;
        cms2[idx] = d_C[(mt * 16 + mm) * 32 + k];
        cns2[idx] = d_C[(nt * 16 + mm) * 32 + k];
    }
    __syncthreads();   // mbar init + coeff staging visible

    const uint32_t CHUNK_BYTES = 2 * 4 * 16 * 32 * 4;   // d1 8KB + d2 8KB

    auto issue = [&](int kc, int s) {
        uint32_t mb = s ? mb1 : mb0;
        mbar_expect(mb, CHUNK_BYTES);
#pragma unroll
        for (int kk = 0; kk < 4; kk++)
            bulk_g2s(sm_addr(&d1s[s][kk * 512]),
                     &d_D1[((size_t)b * 32 + kc * 4 + kk) * NI + nt * 512],
                     2048, mb);
#pragma unroll
        for (int mm = 0; mm < 16; mm++)
            bulk_g2s(sm_addr(&d2s[s][mm * 128]),
                     &d_D2[(((size_t)b * MDIM + mt * 16 + mm) * 32 + kc * 4) * 32],
                     512, mb);
    };

    uint64_t acc[8][4];
#pragma unroll
    for (int j = 0; j < 8; j++)
#pragma unroll
        for (int a = 0; a < 4; a++) acc[j][a] = 0ull;

    if (t == 0) issue(0, 0);
    for (int kc = 0; kc < 8; kc++) {
        int s = kc & 1;
        if (kc + 1 < 8) {
            __syncthreads();                 // readers done with buffer s^1
            if (t == 0) issue(kc + 1, s ^ 1);
        }
        mbar_wait(s ? mb1 : mb0, (kc >> 1) & 1);

        const float* d1b = d1s[s];
        const float* d2b = d2s[s];

#pragma unroll
        for (int kk = 0; kk < 4; kk++) {
            int k = kc * 4 + kk;

            F4U cmA, cmB, cnv;
            cmA.f4 = *(const float4*)&cms2[k * 16 + mp * 8];
            cmB.f4 = *(const float4*)&cms2[k * 16 + mp * 8 + 4];
            cnv.f4 = *(const float4*)&cns2[k * 16 + nq * 4];

            uint64_t cnp[4];
#pragma unroll
            for (int a = 0; a < 4; a++) cnp[a] = pack2(cnv.f[a]);

            F2U d1v[4], d2v[8];
#pragma unroll
            for (int a = 0; a < 4; a++)
                d1v[a].f2 = *(const float2*)&d1b[(kk * 16 + nq * 4 + a) * 32 + io * 2];
#pragma unroll
            for (int j = 0; j < 8; j++)
                d2v[j].f2 = *(const float2*)&d2b[((mp * 8 + j) * 4 + kk) * 32 + io * 2];

            float cmf[8] = {cmA.f[0], cmA.f[1], cmA.f[2], cmA.f[3],
                            cmB.f[0], cmB.f[1], cmB.f[2], cmB.f[3]};
#pragma unroll
            for (int j = 0; j < 8; j++) {
                uint64_t cmp = pack2(cmf[j]);
#pragma unroll
                for (int a = 0; a < 4; a++) {
                    fma2(acc[j][a], cmp, d1v[a].u);
                    fma2(acc[j][a], cnp[a], d2v[j].u);
                }
            }
        }
    }

#pragma unroll
    for (int j = 0; j < 8; j++) {
        int m = mt * 16 + mp * 8 + j;
#pragma unroll
        for (int a = 0; a < 4; a++) {
            int n = nt * 16 + nq * 4 + a;
            F2U v; v.u = acc[j][a];
            *(float2*)&out[((size_t)b * MDIM + m) * NI + n * 32 + io * 2] = v.f2;
        }
    }
}

// ---------------------------------------------------------------------------
extern "C" void kernel_launch(void* const* d_in, const int* in_sizes, int n_in,
                              void* d_out, int out_size) {
    const float* x = (const float*)d_in[0];
    float* out = (float*)d_out;

    init_C_kernel<<<32, 256>>>();
    k1_down_m<<<dim3(32, 8), 128>>>(x);
    k2_down_n<<<dim3(32, 8), 256>>>(x);
    k3_up<<<dim3(16, 16, 8), 128>>>(out);
}